// round 2
// baseline (speedup 1.0000x reference)
#include <cuda_runtime.h>
#include <cuda_bf16.h>
#include <math.h>

#define T_TOK 2048
#define H_DIM 2048
#define NH 16
#define HD 128
#define QKV_N (3 * H_DIM)   // 6144
#define EPS 1e-6f
#define ATT_SCALE 0.08838834764831843f  // 128^-0.5

// ---------------- scratch (static device globals; no allocation) -------------
__device__ float g_qkv[T_TOK * QKV_N];     // [T, 3H]  (q | k | v)
__device__ float g_q[T_TOK * H_DIM];       // [T, NH, HD] post norm+rope
__device__ float g_k[T_TOK * H_DIM];
__device__ float g_attn[T_TOK * H_DIM];    // attention output [T, H]

// ---------------- generic fp32 SGEMM: C[M,N] = A[M,K] @ B[K,N] ---------------
// 128x128 tile, BK=8, 256 threads, 8x8 register tile per thread.
__global__ __launch_bounds__(256) void sgemm128(
    const float* __restrict__ A, const float* __restrict__ B,
    float* __restrict__ C, int M, int N, int K)
{
    __shared__ float As[8][128];
    __shared__ float Bs[8][128];
    const int bx = blockIdx.x;          // N tile
    const int by = blockIdx.y;          // M tile
    const int tid = threadIdx.x;
    const int tx = tid & 15;            // 0..15  (N direction)
    const int ty = tid >> 4;            // 0..15  (M direction)

    const int arow  = tid >> 1;         // 0..127
    const int acol4 = (tid & 1) * 4;    // 0 or 4
    const int brow  = tid >> 5;         // 0..7
    const int bcol4 = (tid & 31) * 4;   // 0..124

    const float* Ab = A + (size_t)(by * 128 + arow) * K + acol4;
    const float* Bb = B + (size_t)brow * N + bx * 128 + bcol4;

    float acc[8][8];
    #pragma unroll
    for (int i = 0; i < 8; i++)
        #pragma unroll
        for (int j = 0; j < 8; j++) acc[i][j] = 0.f;

    for (int kt = 0; kt < K; kt += 8) {
        float4 a4 = *(const float4*)(Ab + kt);
        float4 b4 = *(const float4*)(Bb + (size_t)kt * N);
        As[acol4 + 0][arow] = a4.x;
        As[acol4 + 1][arow] = a4.y;
        As[acol4 + 2][arow] = a4.z;
        As[acol4 + 3][arow] = a4.w;
        *(float4*)&Bs[brow][bcol4] = b4;
        __syncthreads();

        #pragma unroll
        for (int k = 0; k < 8; k++) {
            float a[8], b[8];
            float4 t0 = *(const float4*)&As[k][ty * 8];
            float4 t1 = *(const float4*)&As[k][ty * 8 + 4];
            a[0]=t0.x; a[1]=t0.y; a[2]=t0.z; a[3]=t0.w;
            a[4]=t1.x; a[5]=t1.y; a[6]=t1.z; a[7]=t1.w;
            float4 u0 = *(const float4*)&Bs[k][tx * 8];
            float4 u1 = *(const float4*)&Bs[k][tx * 8 + 4];
            b[0]=u0.x; b[1]=u0.y; b[2]=u0.z; b[3]=u0.w;
            b[4]=u1.x; b[5]=u1.y; b[6]=u1.z; b[7]=u1.w;
            #pragma unroll
            for (int i = 0; i < 8; i++)
                #pragma unroll
                for (int j = 0; j < 8; j++)
                    acc[i][j] = fmaf(a[i], b[j], acc[i][j]);
        }
        __syncthreads();
    }

    #pragma unroll
    for (int i = 0; i < 8; i++) {
        const size_t row = (size_t)(by * 128 + ty * 8 + i);
        #pragma unroll
        for (int j = 0; j < 8; j++)
            C[row * N + bx * 128 + tx * 8 + j] = acc[i][j];
    }
}

// -------------- fused RMSNorm (over full H) + RoPE for q and k ---------------
// one block per token, 256 threads
__global__ __launch_bounds__(256) void norm_rope_kernel(
    const float* __restrict__ qkv, const int* __restrict__ positions,
    const float* __restrict__ qw, const float* __restrict__ kw,
    float* __restrict__ qo, float* __restrict__ ko)
{
    const int t = blockIdx.x;
    const int tid = threadIdx.x;
    const float* row = qkv + (size_t)t * QKV_N;

    __shared__ float red[256];
    __shared__ float s_invq, s_invk;

    float sq = 0.f, sk = 0.f;
    for (int i = tid; i < H_DIM; i += 256) {
        float a = row[i];          sq = fmaf(a, a, sq);
        float b = row[H_DIM + i];  sk = fmaf(b, b, sk);
    }
    // reduce q
    red[tid] = sq; __syncthreads();
    for (int s = 128; s > 0; s >>= 1) {
        if (tid < s) red[tid] += red[tid + s];
        __syncthreads();
    }
    if (tid == 0) s_invq = rsqrtf(red[0] / (float)H_DIM + EPS);
    __syncthreads();
    // reduce k
    red[tid] = sk; __syncthreads();
    for (int s = 128; s > 0; s >>= 1) {
        if (tid < s) red[tid] += red[tid + s];
        __syncthreads();
    }
    if (tid == 0) s_invk = rsqrtf(red[0] / (float)H_DIM + EPS);
    __syncthreads();

    const float invq = s_invq, invk = s_invk;
    const float pos = (float)positions[t];

    // 16 heads * 64 rotation pairs = 1024 pairs
    for (int p = tid; p < NH * (HD / 2); p += 256) {
        const int h = p >> 6;
        const int d = p & 63;
        // inv_freq = theta^(-d/64)
        float invf = powf(500000.0f, -(float)d / 64.0f);
        float ang = pos * invf;
        float c = cosf(ang), s = sinf(ang);

        const int i1 = h * HD + d;
        const int i2 = i1 + 64;

        float q1 = row[i1] * invq * qw[i1];
        float q2 = row[i2] * invq * qw[i2];
        float k1 = row[H_DIM + i1] * invk * kw[i1];
        float k2 = row[H_DIM + i2] * invk * kw[i2];

        const size_t ob = ((size_t)t * NH + h) * HD;
        qo[ob + d]      = q1 * c - q2 * s;
        qo[ob + d + 64] = q2 * c + q1 * s;
        ko[ob + d]      = k1 * c - k2 * s;
        ko[ob + d + 64] = k2 * c + k1 * s;
    }
}

// ---------------------------- flash attention fp32 ---------------------------
// grid: (32 q-tiles, 16 heads), 256 threads
// q tile 64 rows, k tiles of 64, online softmax, HD=128.
#define QS_STRIDE 129
#define S_STRIDE 65
#define FLASH_SMEM_FLOATS (3 * 64 * QS_STRIDE + 64 * S_STRIDE + 3 * 64)

__global__ __launch_bounds__(256) void flash_kernel(
    const float* __restrict__ qg, const float* __restrict__ kg,
    const float* __restrict__ qkv, float* __restrict__ og)
{
    const int qt  = blockIdx.x;
    const int h   = blockIdx.y;
    const int tid = threadIdx.x;

    extern __shared__ float sm[];
    float* qs   = sm;                        // 64 x 129
    float* ks   = qs + 64 * QS_STRIDE;       // 64 x 129
    float* vs   = ks + 64 * QS_STRIDE;       // 64 x 129
    float* S    = vs + 64 * QS_STRIDE;       // 64 x 65
    float* mrow = S + 64 * S_STRIDE;         // 64
    float* lrow = mrow + 64;                 // 64
    float* arow = lrow + 64;                 // 64

    // load q tile
    for (int idx = tid; idx < 64 * 128; idx += 256) {
        const int r = idx >> 7, d = idx & 127;
        qs[r * QS_STRIDE + d] = qg[(((size_t)(qt * 64 + r)) * NH + h) * HD + d];
    }
    if (tid < 64) { mrow[tid] = -1e30f; lrow[tid] = 0.f; }
    __syncthreads();

    const int tr = tid >> 4;   // 0..15 : rows tr*4 .. tr*4+3
    const int tc = tid & 15;   // 0..15 : cols tc + 16*j

    float acc[4][8];
    #pragma unroll
    for (int i = 0; i < 4; i++)
        #pragma unroll
        for (int c = 0; c < 8; c++) acc[i][c] = 0.f;

    for (int kb = 0; kb <= qt; kb++) {
        // load K / V tiles
        for (int idx = tid; idx < 64 * 128; idx += 256) {
            const int r = idx >> 7, d = idx & 127;
            ks[r * QS_STRIDE + d] = kg[(((size_t)(kb * 64 + r)) * NH + h) * HD + d];
            vs[r * QS_STRIDE + d] =
                qkv[(size_t)(kb * 64 + r) * QKV_N + 2 * H_DIM + h * HD + d];
        }
        __syncthreads();

        // scores S = Q K^T (thread computes rows tr*4+i, cols tc+16*j)
        float sacc[4][4];
        #pragma unroll
        for (int i = 0; i < 4; i++)
            #pragma unroll
            for (int j = 0; j < 4; j++) sacc[i][j] = 0.f;

        #pragma unroll 4
        for (int d = 0; d < 128; d++) {
            float a0 = qs[(tr * 4 + 0) * QS_STRIDE + d];
            float a1 = qs[(tr * 4 + 1) * QS_STRIDE + d];
            float a2 = qs[(tr * 4 + 2) * QS_STRIDE + d];
            float a3 = qs[(tr * 4 + 3) * QS_STRIDE + d];
            float b0 = ks[(tc +  0) * QS_STRIDE + d];
            float b1 = ks[(tc + 16) * QS_STRIDE + d];
            float b2 = ks[(tc + 32) * QS_STRIDE + d];
            float b3 = ks[(tc + 48) * QS_STRIDE + d];
            sacc[0][0]=fmaf(a0,b0,sacc[0][0]); sacc[0][1]=fmaf(a0,b1,sacc[0][1]);
            sacc[0][2]=fmaf(a0,b2,sacc[0][2]); sacc[0][3]=fmaf(a0,b3,sacc[0][3]);
            sacc[1][0]=fmaf(a1,b0,sacc[1][0]); sacc[1][1]=fmaf(a1,b1,sacc[1][1]);
            sacc[1][2]=fmaf(a1,b2,sacc[1][2]); sacc[1][3]=fmaf(a1,b3,sacc[1][3]);
            sacc[2][0]=fmaf(a2,b0,sacc[2][0]); sacc[2][1]=fmaf(a2,b1,sacc[2][1]);
            sacc[2][2]=fmaf(a2,b2,sacc[2][2]); sacc[2][3]=fmaf(a2,b3,sacc[2][3]);
            sacc[3][0]=fmaf(a3,b0,sacc[3][0]); sacc[3][1]=fmaf(a3,b1,sacc[3][1]);
            sacc[3][2]=fmaf(a3,b2,sacc[3][2]); sacc[3][3]=fmaf(a3,b3,sacc[3][3]);
        }

        // write masked+scaled scores
        #pragma unroll
        for (int i = 0; i < 4; i++) {
            const int gi = qt * 64 + tr * 4 + i;
            #pragma unroll
            for (int j = 0; j < 4; j++) {
                const int cj = tc + 16 * j;
                const int gj = kb * 64 + cj;
                float v = sacc[i][j] * ATT_SCALE;
                if (gj > gi) v = -1e30f;
                S[(tr * 4 + i) * S_STRIDE + cj] = v;
            }
        }
        __syncthreads();

        // online softmax row update (one thread per row)
        if (tid < 64) {
            const int r = tid;
            float m_old = mrow[r];
            float mx = m_old;
            #pragma unroll 8
            for (int j = 0; j < 64; j++) mx = fmaxf(mx, S[r * S_STRIDE + j]);
            float alpha = __expf(m_old - mx);
            float psum = 0.f;
            #pragma unroll 8
            for (int j = 0; j < 64; j++) {
                float p = __expf(S[r * S_STRIDE + j] - mx);
                S[r * S_STRIDE + j] = p;
                psum += p;
            }
            mrow[r] = mx;
            lrow[r] = lrow[r] * alpha + psum;
            arow[r] = alpha;
        }
        __syncthreads();

        // rescale accumulators and add P @ V
        #pragma unroll
        for (int i = 0; i < 4; i++) {
            float al = arow[tr * 4 + i];
            #pragma unroll
            for (int c = 0; c < 8; c++) acc[i][c] *= al;
        }
        for (int j = 0; j < 64; j++) {
            float p0 = S[(tr * 4 + 0) * S_STRIDE + j];
            float p1 = S[(tr * 4 + 1) * S_STRIDE + j];
            float p2 = S[(tr * 4 + 2) * S_STRIDE + j];
            float p3 = S[(tr * 4 + 3) * S_STRIDE + j];
            float v[8];
            #pragma unroll
            for (int c = 0; c < 8; c++) v[c] = vs[j * QS_STRIDE + tc + 16 * c];
            #pragma unroll
            for (int c = 0; c < 8; c++) {
                acc[0][c] = fmaf(p0, v[c], acc[0][c]);
                acc[1][c] = fmaf(p1, v[c], acc[1][c]);
                acc[2][c] = fmaf(p2, v[c], acc[2][c]);
                acc[3][c] = fmaf(p3, v[c], acc[3][c]);
            }
        }
        __syncthreads();
    }

    // final normalize + store
    #pragma unroll
    for (int i = 0; i < 4; i++) {
        const int r = tr * 4 + i;
        const float linv = 1.f / lrow[r];
        #pragma unroll
        for (int c = 0; c < 8; c++)
            og[(size_t)(qt * 64 + r) * H_DIM + h * HD + tc + 16 * c] =
                acc[i][c] * linv;
    }
}

// --------------------------------- launcher ----------------------------------
extern "C" void kernel_launch(void* const* d_in, const int* in_sizes, int n_in,
                              void* d_out, int out_size)
{
    const int*   positions = (const int*)  d_in[0];
    const float* hidden    = (const float*)d_in[1];
    const float* w_qkv     = (const float*)d_in[2];
    const float* q_norm_w  = (const float*)d_in[3];
    const float* k_norm_w  = (const float*)d_in[4];
    const float* w_o       = (const float*)d_in[5];
    float* out = (float*)d_out;

    float *qkv, *q, *k, *attn;
    cudaGetSymbolAddress((void**)&qkv,  g_qkv);
    cudaGetSymbolAddress((void**)&q,    g_q);
    cudaGetSymbolAddress((void**)&k,    g_k);
    cudaGetSymbolAddress((void**)&attn, g_attn);

    // 1) QKV projection: [2048,2048] @ [2048,6144]
    {
        dim3 grid(QKV_N / 128, T_TOK / 128);
        sgemm128<<<grid, 256>>>(hidden, w_qkv, qkv, T_TOK, QKV_N, H_DIM);
    }

    // 2) RMSNorm + RoPE
    norm_rope_kernel<<<T_TOK, 256>>>(qkv, positions, q_norm_w, k_norm_w, q, k);

    // 3) causal flash attention
    {
        const int smem = FLASH_SMEM_FLOATS * sizeof(float);
        cudaFuncSetAttribute(flash_kernel,
                             cudaFuncAttributeMaxDynamicSharedMemorySize, smem);
        dim3 grid(T_TOK / 64, NH);
        flash_kernel<<<grid, 256, smem>>>(q, k, qkv, attn);
    }

    // 4) output projection: [2048,2048] @ [2048,2048]
    {
        dim3 grid(H_DIM / 128, T_TOK / 128);
        sgemm128<<<grid, 256>>>(attn, w_o, out, T_TOK, H_DIM, H_DIM);
    }
}

// round 4
// speedup vs baseline: 2.1482x; 2.1482x over previous
#include <cuda_runtime.h>
#include <cuda_fp16.h>
#include <cuda_bf16.h>
#include <stdint.h>
#include <math.h>

typedef unsigned int u32;

#define T_TOK 2048
#define H_DIM 2048
#define NH 16
#define HD 128
#define QKV_N (3 * H_DIM)   // 6144
#define EPS 1e-6f
#define ATT_SCALE 0.08838834764831843f  // 128^-0.5

// ---------------- scratch (static device globals; no allocation) -------------
__device__ float  g_qkv[T_TOK * QKV_N];     // [T, 3H]  (q | k | v) fp32
__device__ float  g_q[T_TOK * H_DIM];       // post norm+rope fp32
__device__ float  g_k[T_TOK * H_DIM];
__device__ float  g_attn[T_TOK * H_DIM];    // attention output fp32
__device__ __half g_hid_h[T_TOK * H_DIM];   // fp16 copies for tensor-core GEMM
__device__ __half g_wqkv_h[H_DIM * QKV_N];
__device__ __half g_wo_h[H_DIM * H_DIM];
__device__ __half g_attn_h[T_TOK * H_DIM];

// ------------------------- f32 -> f16 conversion -----------------------------
__global__ __launch_bounds__(256) void f32_to_f16(
    const float* __restrict__ in, __half* __restrict__ out, int n4)
{
    int i = blockIdx.x * 256 + threadIdx.x;
    if (i < n4) {
        float4 v = ((const float4*)in)[i];
        __half2 h0 = __floats2half2_rn(v.x, v.y);
        __half2 h1 = __floats2half2_rn(v.z, v.w);
        ((__half2*)out)[2 * i]     = h0;
        ((__half2*)out)[2 * i + 1] = h1;
    }
}

// ------------- fp16 tensor-core GEMM: C[M,N] = A[M,K] @ B[K,N] ---------------
// 128x128 block tile, BK=32, 256 threads (8 warps), warp tile 64x32,
// mma.sync m16n8k16 f16 -> f32, cp.async double-buffered smem.
#define ASTRIDE 40    // halves: 80B rows  (odd multiple of 16B -> ldmatrix conflict-free)
#define BSTRIDE 136   // halves: 272B rows (odd multiple of 16B)

__device__ __forceinline__ void cp_async16(void* sptr, const void* gptr) {
    u32 s = (u32)__cvta_generic_to_shared(sptr);
    asm volatile("cp.async.cg.shared.global [%0], [%1], 16;\n" :: "r"(s), "l"(gptr));
}
__device__ __forceinline__ void cp_commit() {
    asm volatile("cp.async.commit_group;\n");
}
__device__ __forceinline__ void cp_wait0() {
    asm volatile("cp.async.wait_group 0;\n");
}
__device__ __forceinline__ void ldmatrix_x4(u32* r, const void* sptr) {
    u32 s = (u32)__cvta_generic_to_shared(sptr);
    asm volatile("ldmatrix.sync.aligned.m8n8.x4.shared.b16 {%0,%1,%2,%3}, [%4];\n"
                 : "=r"(r[0]), "=r"(r[1]), "=r"(r[2]), "=r"(r[3]) : "r"(s));
}
__device__ __forceinline__ void ldmatrix_x4_trans(u32* r, const void* sptr) {
    u32 s = (u32)__cvta_generic_to_shared(sptr);
    asm volatile("ldmatrix.sync.aligned.m8n8.x4.trans.shared.b16 {%0,%1,%2,%3}, [%4];\n"
                 : "=r"(r[0]), "=r"(r[1]), "=r"(r[2]), "=r"(r[3]) : "r"(s));
}
__device__ __forceinline__ void mma16816(float* d, const u32* a, const u32* b) {
    asm volatile(
        "mma.sync.aligned.m16n8k16.row.col.f32.f16.f16.f32 "
        "{%0,%1,%2,%3}, {%4,%5,%6,%7}, {%8,%9}, {%0,%1,%2,%3};\n"
        : "+f"(d[0]), "+f"(d[1]), "+f"(d[2]), "+f"(d[3])
        : "r"(a[0]), "r"(a[1]), "r"(a[2]), "r"(a[3]), "r"(b[0]), "r"(b[1]));
}

__global__ __launch_bounds__(256) void hgemm128(
    const __half* __restrict__ A, const __half* __restrict__ B,
    float* __restrict__ C, int M, int N, int K)
{
    __shared__ __align__(16) __half As[2][128 * ASTRIDE];
    __shared__ __align__(16) __half Bs[2][32 * BSTRIDE];

    const int tid  = threadIdx.x;
    const int wid  = tid >> 5;
    const int lane = tid & 31;
    const int wm = (wid & 1) * 64;   // warp M offset in tile
    const int wn = (wid >> 1) * 32;  // warp N offset in tile
    const int bRow = blockIdx.y * 128;
    const int bCol = blockIdx.x * 128;

    // global->smem load indices (16B chunks)
    const int a_row0   = tid >> 2;          // A: 128 rows x 4 chunks, 2 per thread
    const int a_chunk0 = (tid & 3) * 8;
    const int b_row0   = tid >> 4;          // B: 32 rows x 16 chunks, 2 per thread
    const int b_chunk0 = (tid & 15) * 8;

    float acc[4][4][4];
    #pragma unroll
    for (int mi = 0; mi < 4; mi++)
        #pragma unroll
        for (int nf = 0; nf < 4; nf++)
            #pragma unroll
            for (int r = 0; r < 4; r++) acc[mi][nf][r] = 0.f;

    const int NT = K / 32;

    // prologue: load tile 0 into buffer 0
    {
        #pragma unroll
        for (int p = 0; p < 2; p++) {
            int ar = a_row0 + p * 64;
            cp_async16(&As[0][ar * ASTRIDE + a_chunk0],
                       A + (size_t)(bRow + ar) * K + a_chunk0);
            int br = b_row0 + p * 16;
            cp_async16(&Bs[0][br * BSTRIDE + b_chunk0],
                       B + (size_t)br * N + bCol + b_chunk0);
        }
        cp_commit();
    }

    for (int kt = 0; kt < NT; kt++) {
        cp_wait0();
        __syncthreads();

        if (kt + 1 < NT) {
            const int nb = (kt + 1) & 1;
            const int kbase = (kt + 1) * 32;
            #pragma unroll
            for (int p = 0; p < 2; p++) {
                int ar = a_row0 + p * 64;
                cp_async16(&As[nb][ar * ASTRIDE + a_chunk0],
                           A + (size_t)(bRow + ar) * K + kbase + a_chunk0);
                int br = b_row0 + p * 16;
                cp_async16(&Bs[nb][br * BSTRIDE + b_chunk0],
                           B + (size_t)(kbase + br) * N + bCol + b_chunk0);
            }
            cp_commit();
        }

        const int cb = kt & 1;
        #pragma unroll
        for (int ko = 0; ko < 32; ko += 16) {
            u32 a[4][4];
            #pragma unroll
            for (int mi = 0; mi < 4; mi++)
                ldmatrix_x4(a[mi],
                    &As[cb][(wm + mi * 16 + (lane & 15)) * ASTRIDE + ko + (lane >> 4) * 8]);
            u32 b[4][2];
            #pragma unroll
            for (int jp = 0; jp < 2; jp++) {
                u32 r[4];
                ldmatrix_x4_trans(r,
                    &Bs[cb][(ko + (lane & 15)) * BSTRIDE + wn + jp * 16 + (lane >> 4) * 8]);
                b[jp * 2][0]     = r[0]; b[jp * 2][1]     = r[1];
                b[jp * 2 + 1][0] = r[2]; b[jp * 2 + 1][1] = r[3];
            }
            #pragma unroll
            for (int mi = 0; mi < 4; mi++)
                #pragma unroll
                for (int nf = 0; nf < 4; nf++)
                    mma16816(acc[mi][nf], a[mi], b[nf]);
        }
        __syncthreads();
    }

    // epilogue
    #pragma unroll
    for (int mi = 0; mi < 4; mi++) {
        const int row0 = bRow + wm + mi * 16 + (lane >> 2);
        #pragma unroll
        for (int nf = 0; nf < 4; nf++) {
            const int col = bCol + wn + nf * 8 + (lane & 3) * 2;
            C[(size_t)row0 * N + col]           = acc[mi][nf][0];
            C[(size_t)row0 * N + col + 1]       = acc[mi][nf][1];
            C[(size_t)(row0 + 8) * N + col]     = acc[mi][nf][2];
            C[(size_t)(row0 + 8) * N + col + 1] = acc[mi][nf][3];
        }
    }
}

// -------------- fused RMSNorm (over full H) + RoPE for q and k ---------------
__global__ __launch_bounds__(256) void norm_rope_kernel(
    const float* __restrict__ qkv, const int* __restrict__ positions,
    const float* __restrict__ qw, const float* __restrict__ kw,
    float* __restrict__ qo, float* __restrict__ ko)
{
    const int t = blockIdx.x;
    const int tid = threadIdx.x;
    const float* row = qkv + (size_t)t * QKV_N;

    __shared__ float red[256];
    __shared__ float s_invq, s_invk;

    float sq = 0.f, sk = 0.f;
    for (int i = tid; i < H_DIM; i += 256) {
        float a = row[i];          sq = fmaf(a, a, sq);
        float b = row[H_DIM + i];  sk = fmaf(b, b, sk);
    }
    red[tid] = sq; __syncthreads();
    for (int s = 128; s > 0; s >>= 1) {
        if (tid < s) red[tid] += red[tid + s];
        __syncthreads();
    }
    if (tid == 0) s_invq = rsqrtf(red[0] / (float)H_DIM + EPS);
    __syncthreads();
    red[tid] = sk; __syncthreads();
    for (int s = 128; s > 0; s >>= 1) {
        if (tid < s) red[tid] += red[tid + s];
        __syncthreads();
    }
    if (tid == 0) s_invk = rsqrtf(red[0] / (float)H_DIM + EPS);
    __syncthreads();

    const float invq = s_invq, invk = s_invk;
    const float pos = (float)positions[t];

    for (int p = tid; p < NH * (HD / 2); p += 256) {
        const int h = p >> 6;
        const int d = p & 63;
        // inv_freq = 500000^(-d/64) = 2^(-d * log2(5e5)/64)
        float invf = exp2f(-0.29580576f * (float)d);
        float ang = pos * invf;
        float c, s;
        sincosf(ang, &s, &c);

        const int i1 = h * HD + d;
        const int i2 = i1 + 64;

        float q1 = row[i1] * invq * qw[i1];
        float q2 = row[i2] * invq * qw[i2];
        float k1 = row[H_DIM + i1] * invk * kw[i1];
        float k2 = row[H_DIM + i2] * invk * kw[i2];

        const size_t ob = ((size_t)t * NH + h) * HD;
        qo[ob + d]      = q1 * c - q2 * s;
        qo[ob + d + 64] = q2 * c + q1 * s;
        ko[ob + d]      = k1 * c - k2 * s;
        ko[ob + d + 64] = k2 * c + k1 * s;
    }
}

// ---------------------------- flash attention fp32 ---------------------------
#define QS_STRIDE 129
#define S_STRIDE 65
#define FLASH_SMEM_FLOATS (3 * 64 * QS_STRIDE + 64 * S_STRIDE + 3 * 64)

__global__ __launch_bounds__(256) void flash_kernel(
    const float* __restrict__ qg, const float* __restrict__ kg,
    const float* __restrict__ qkv, float* __restrict__ og)
{
    const int qt  = blockIdx.x;
    const int h   = blockIdx.y;
    const int tid = threadIdx.x;

    extern __shared__ float sm[];
    float* qs   = sm;
    float* ks   = qs + 64 * QS_STRIDE;
    float* vs   = ks + 64 * QS_STRIDE;
    float* S    = vs + 64 * QS_STRIDE;
    float* mrow = S + 64 * S_STRIDE;
    float* lrow = mrow + 64;
    float* arow = lrow + 64;

    for (int idx = tid; idx < 64 * 128; idx += 256) {
        const int r = idx >> 7, d = idx & 127;
        qs[r * QS_STRIDE + d] = qg[(((size_t)(qt * 64 + r)) * NH + h) * HD + d];
    }
    if (tid < 64) { mrow[tid] = -1e30f; lrow[tid] = 0.f; }
    __syncthreads();

    const int tr = tid >> 4;
    const int tc = tid & 15;

    float acc[4][8];
    #pragma unroll
    for (int i = 0; i < 4; i++)
        #pragma unroll
        for (int c = 0; c < 8; c++) acc[i][c] = 0.f;

    for (int kb = 0; kb <= qt; kb++) {
        for (int idx = tid; idx < 64 * 128; idx += 256) {
            const int r = idx >> 7, d = idx & 127;
            ks[r * QS_STRIDE + d] = kg[(((size_t)(kb * 64 + r)) * NH + h) * HD + d];
            vs[r * QS_STRIDE + d] =
                qkv[(size_t)(kb * 64 + r) * QKV_N + 2 * H_DIM + h * HD + d];
        }
        __syncthreads();

        float sacc[4][4];
        #pragma unroll
        for (int i = 0; i < 4; i++)
            #pragma unroll
            for (int j = 0; j < 4; j++) sacc[i][j] = 0.f;

        #pragma unroll 4
        for (int d = 0; d < 128; d++) {
            float a0 = qs[(tr * 4 + 0) * QS_STRIDE + d];
            float a1 = qs[(tr * 4 + 1) * QS_STRIDE + d];
            float a2 = qs[(tr * 4 + 2) * QS_STRIDE + d];
            float a3 = qs[(tr * 4 + 3) * QS_STRIDE + d];
            float b0 = ks[(tc +  0) * QS_STRIDE + d];
            float b1 = ks[(tc + 16) * QS_STRIDE + d];
            float b2 = ks[(tc + 32) * QS_STRIDE + d];
            float b3 = ks[(tc + 48) * QS_STRIDE + d];
            sacc[0][0]=fmaf(a0,b0,sacc[0][0]); sacc[0][1]=fmaf(a0,b1,sacc[0][1]);
            sacc[0][2]=fmaf(a0,b2,sacc[0][2]); sacc[0][3]=fmaf(a0,b3,sacc[0][3]);
            sacc[1][0]=fmaf(a1,b0,sacc[1][0]); sacc[1][1]=fmaf(a1,b1,sacc[1][1]);
            sacc[1][2]=fmaf(a1,b2,sacc[1][2]); sacc[1][3]=fmaf(a1,b3,sacc[1][3]);
            sacc[2][0]=fmaf(a2,b0,sacc[2][0]); sacc[2][1]=fmaf(a2,b1,sacc[2][1]);
            sacc[2][2]=fmaf(a2,b2,sacc[2][2]); sacc[2][3]=fmaf(a2,b3,sacc[2][3]);
            sacc[3][0]=fmaf(a3,b0,sacc[3][0]); sacc[3][1]=fmaf(a3,b1,sacc[3][1]);
            sacc[3][2]=fmaf(a3,b2,sacc[3][2]); sacc[3][3]=fmaf(a3,b3,sacc[3][3]);
        }

        #pragma unroll
        for (int i = 0; i < 4; i++) {
            const int gi = qt * 64 + tr * 4 + i;
            #pragma unroll
            for (int j = 0; j < 4; j++) {
                const int cj = tc + 16 * j;
                const int gj = kb * 64 + cj;
                float v = sacc[i][j] * ATT_SCALE;
                if (gj > gi) v = -1e30f;
                S[(tr * 4 + i) * S_STRIDE + cj] = v;
            }
        }
        __syncthreads();

        if (tid < 64) {
            const int r = tid;
            float m_old = mrow[r];
            float mx = m_old;
            #pragma unroll 8
            for (int j = 0; j < 64; j++) mx = fmaxf(mx, S[r * S_STRIDE + j]);
            float alpha = __expf(m_old - mx);
            float psum = 0.f;
            #pragma unroll 8
            for (int j = 0; j < 64; j++) {
                float p = __expf(S[r * S_STRIDE + j] - mx);
                S[r * S_STRIDE + j] = p;
                psum += p;
            }
            mrow[r] = mx;
            lrow[r] = lrow[r] * alpha + psum;
            arow[r] = alpha;
        }
        __syncthreads();

        #pragma unroll
        for (int i = 0; i < 4; i++) {
            float al = arow[tr * 4 + i];
            #pragma unroll
            for (int c = 0; c < 8; c++) acc[i][c] *= al;
        }
        for (int j = 0; j < 64; j++) {
            float p0 = S[(tr * 4 + 0) * S_STRIDE + j];
            float p1 = S[(tr * 4 + 1) * S_STRIDE + j];
            float p2 = S[(tr * 4 + 2) * S_STRIDE + j];
            float p3 = S[(tr * 4 + 3) * S_STRIDE + j];
            float v[8];
            #pragma unroll
            for (int c = 0; c < 8; c++) v[c] = vs[j * QS_STRIDE + tc + 16 * c];
            #pragma unroll
            for (int c = 0; c < 8; c++) {
                acc[0][c] = fmaf(p0, v[c], acc[0][c]);
                acc[1][c] = fmaf(p1, v[c], acc[1][c]);
                acc[2][c] = fmaf(p2, v[c], acc[2][c]);
                acc[3][c] = fmaf(p3, v[c], acc[3][c]);
            }
        }
        __syncthreads();
    }

    #pragma unroll
    for (int i = 0; i < 4; i++) {
        const int r = tr * 4 + i;
        const float linv = 1.f / lrow[r];
        #pragma unroll
        for (int c = 0; c < 8; c++)
            og[(size_t)(qt * 64 + r) * H_DIM + h * HD + tc + 16 * c] =
                acc[i][c] * linv;
    }
}

// --------------------------------- launcher ----------------------------------
extern "C" void kernel_launch(void* const* d_in, const int* in_sizes, int n_in,
                              void* d_out, int out_size)
{
    const int*   positions = (const int*)  d_in[0];
    const float* hidden    = (const float*)d_in[1];
    const float* w_qkv     = (const float*)d_in[2];
    const float* q_norm_w  = (const float*)d_in[3];
    const float* k_norm_w  = (const float*)d_in[4];
    const float* w_o       = (const float*)d_in[5];
    float* out = (float*)d_out;

    float *qkv, *q, *k, *attn;
    __half *hid_h, *wqkv_h, *wo_h, *attn_h;
    cudaGetSymbolAddress((void**)&qkv,    g_qkv);
    cudaGetSymbolAddress((void**)&q,      g_q);
    cudaGetSymbolAddress((void**)&k,      g_k);
    cudaGetSymbolAddress((void**)&attn,   g_attn);
    cudaGetSymbolAddress((void**)&hid_h,  g_hid_h);
    cudaGetSymbolAddress((void**)&wqkv_h, g_wqkv_h);
    cudaGetSymbolAddress((void**)&wo_h,   g_wo_h);
    cudaGetSymbolAddress((void**)&attn_h, g_attn_h);

    // 0) fp32 -> fp16 conversions for GEMM operands
    {
        int n4 = (T_TOK * H_DIM) / 4;
        f32_to_f16<<<(n4 + 255) / 256, 256>>>(hidden, hid_h, n4);
        int n4w = (H_DIM * QKV_N) / 4;
        f32_to_f16<<<(n4w + 255) / 256, 256>>>(w_qkv, wqkv_h, n4w);
        int n4o = (H_DIM * H_DIM) / 4;
        f32_to_f16<<<(n4o + 255) / 256, 256>>>(w_o, wo_h, n4o);
    }

    // 1) QKV projection (fp16 tensor cores): [2048,2048] @ [2048,6144]
    {
        dim3 grid(QKV_N / 128, T_TOK / 128);
        hgemm128<<<grid, 256>>>(hid_h, wqkv_h, qkv, T_TOK, QKV_N, H_DIM);
    }

    // 2) RMSNorm + RoPE
    norm_rope_kernel<<<T_TOK, 256>>>(qkv, positions, q_norm_w, k_norm_w, q, k);

    // 3) causal flash attention (fp32)
    {
        const int smem = FLASH_SMEM_FLOATS * sizeof(float);
        cudaFuncSetAttribute(flash_kernel,
                             cudaFuncAttributeMaxDynamicSharedMemorySize, smem);
        dim3 grid(T_TOK / 64, NH);
        flash_kernel<<<grid, 256, smem>>>(q, k, qkv, attn);
    }

    // 4) output projection (fp16 tensor cores): [2048,2048] @ [2048,2048]
    {
        int n4 = (T_TOK * H_DIM) / 4;
        f32_to_f16<<<(n4 + 255) / 256, 256>>>(attn, attn_h, n4);
        dim3 grid(H_DIM / 128, T_TOK / 128);
        hgemm128<<<grid, 256>>>(attn_h, wo_h, out, T_TOK, H_DIM, H_DIM);
    }
}

// round 5
// speedup vs baseline: 6.4555x; 3.0050x over previous
#include <cuda_runtime.h>
#include <cuda_fp16.h>
#include <cuda_bf16.h>
#include <stdint.h>
#include <math.h>

typedef unsigned int u32;

#define T_TOK 2048
#define H_DIM 2048
#define NH 16
#define HD 128
#define QKV_N (3 * H_DIM)   // 6144
#define EPS 1e-6f
#define ATT_SCALE 0.08838834764831843f  // 128^-0.5

// ---------------- scratch (static device globals; no allocation) -------------
__device__ float  g_qkv[T_TOK * QKV_N];     // [T, 3H]  (q | k | v) fp32
__device__ __half g_qh[T_TOK * H_DIM];      // post norm+rope, pre-scaled by ATT_SCALE
__device__ __half g_kh[T_TOK * H_DIM];
__device__ __half g_vh[T_TOK * H_DIM];
__device__ __half g_hid_h[T_TOK * H_DIM];
__device__ __half g_wqkv_h[H_DIM * QKV_N];
__device__ __half g_wo_h[H_DIM * H_DIM];
__device__ __half g_attn_h[T_TOK * H_DIM];

// ------------------------- f32 -> f16 conversion -----------------------------
__global__ __launch_bounds__(256) void f32_to_f16(
    const float* __restrict__ in, __half* __restrict__ out, int n4)
{
    int i = blockIdx.x * 256 + threadIdx.x;
    if (i < n4) {
        float4 v = ((const float4*)in)[i];
        ((__half2*)out)[2 * i]     = __floats2half2_rn(v.x, v.y);
        ((__half2*)out)[2 * i + 1] = __floats2half2_rn(v.z, v.w);
    }
}

// ------------------------- PTX wrappers --------------------------------------
__device__ __forceinline__ void cp_async16(void* sptr, const void* gptr) {
    u32 s = (u32)__cvta_generic_to_shared(sptr);
    asm volatile("cp.async.cg.shared.global [%0], [%1], 16;\n" :: "r"(s), "l"(gptr));
}
__device__ __forceinline__ void cp_commit() {
    asm volatile("cp.async.commit_group;\n");
}
__device__ __forceinline__ void cp_wait0() {
    asm volatile("cp.async.wait_group 0;\n");
}
__device__ __forceinline__ void ldmatrix_x4(u32* r, const void* sptr) {
    u32 s = (u32)__cvta_generic_to_shared(sptr);
    asm volatile("ldmatrix.sync.aligned.m8n8.x4.shared.b16 {%0,%1,%2,%3}, [%4];\n"
                 : "=r"(r[0]), "=r"(r[1]), "=r"(r[2]), "=r"(r[3]) : "r"(s));
}
__device__ __forceinline__ void ldmatrix_x4_trans(u32* r, const void* sptr) {
    u32 s = (u32)__cvta_generic_to_shared(sptr);
    asm volatile("ldmatrix.sync.aligned.m8n8.x4.trans.shared.b16 {%0,%1,%2,%3}, [%4];\n"
                 : "=r"(r[0]), "=r"(r[1]), "=r"(r[2]), "=r"(r[3]) : "r"(s));
}
__device__ __forceinline__ void mma16816(float* d, const u32* a, const u32* b) {
    asm volatile(
        "mma.sync.aligned.m16n8k16.row.col.f32.f16.f16.f32 "
        "{%0,%1,%2,%3}, {%4,%5,%6,%7}, {%8,%9}, {%0,%1,%2,%3};\n"
        : "+f"(d[0]), "+f"(d[1]), "+f"(d[2]), "+f"(d[3])
        : "r"(a[0]), "r"(a[1]), "r"(a[2]), "r"(a[3]), "r"(b[0]), "r"(b[1]));
}
__device__ __forceinline__ u32 packh2(float a, float b) {
    __half2 h = __floats2half2_rn(a, b);
    return *reinterpret_cast<u32*>(&h);
}

// ------------- fp16 tensor-core GEMM: C[M,N] = A[M,K] @ B[K,N] ---------------
#define ASTRIDE 40
#define BSTRIDE 136

__global__ __launch_bounds__(256) void hgemm128(
    const __half* __restrict__ A, const __half* __restrict__ B,
    float* __restrict__ C, int M, int N, int K)
{
    __shared__ __align__(16) __half As[2][128 * ASTRIDE];
    __shared__ __align__(16) __half Bs[2][32 * BSTRIDE];

    const int tid  = threadIdx.x;
    const int wid  = tid >> 5;
    const int lane = tid & 31;
    const int wm = (wid & 1) * 64;
    const int wn = (wid >> 1) * 32;
    const int bRow = blockIdx.y * 128;
    const int bCol = blockIdx.x * 128;

    const int a_row0   = tid >> 2;
    const int a_chunk0 = (tid & 3) * 8;
    const int b_row0   = tid >> 4;
    const int b_chunk0 = (tid & 15) * 8;

    float acc[4][4][4];
    #pragma unroll
    for (int mi = 0; mi < 4; mi++)
        #pragma unroll
        for (int nf = 0; nf < 4; nf++)
            #pragma unroll
            for (int r = 0; r < 4; r++) acc[mi][nf][r] = 0.f;

    const int NT = K / 32;

    {
        #pragma unroll
        for (int p = 0; p < 2; p++) {
            int ar = a_row0 + p * 64;
            cp_async16(&As[0][ar * ASTRIDE + a_chunk0],
                       A + (size_t)(bRow + ar) * K + a_chunk0);
            int br = b_row0 + p * 16;
            cp_async16(&Bs[0][br * BSTRIDE + b_chunk0],
                       B + (size_t)br * N + bCol + b_chunk0);
        }
        cp_commit();
    }

    for (int kt = 0; kt < NT; kt++) {
        cp_wait0();
        __syncthreads();

        if (kt + 1 < NT) {
            const int nb = (kt + 1) & 1;
            const int kbase = (kt + 1) * 32;
            #pragma unroll
            for (int p = 0; p < 2; p++) {
                int ar = a_row0 + p * 64;
                cp_async16(&As[nb][ar * ASTRIDE + a_chunk0],
                           A + (size_t)(bRow + ar) * K + kbase + a_chunk0);
                int br = b_row0 + p * 16;
                cp_async16(&Bs[nb][br * BSTRIDE + b_chunk0],
                           B + (size_t)(kbase + br) * N + bCol + b_chunk0);
            }
            cp_commit();
        }

        const int cb = kt & 1;
        #pragma unroll
        for (int ko = 0; ko < 32; ko += 16) {
            u32 a[4][4];
            #pragma unroll
            for (int mi = 0; mi < 4; mi++)
                ldmatrix_x4(a[mi],
                    &As[cb][(wm + mi * 16 + (lane & 15)) * ASTRIDE + ko + (lane >> 4) * 8]);
            u32 b[4][2];
            #pragma unroll
            for (int jp = 0; jp < 2; jp++) {
                u32 r[4];
                ldmatrix_x4_trans(r,
                    &Bs[cb][(ko + (lane & 15)) * BSTRIDE + wn + jp * 16 + (lane >> 4) * 8]);
                b[jp * 2][0]     = r[0]; b[jp * 2][1]     = r[1];
                b[jp * 2 + 1][0] = r[2]; b[jp * 2 + 1][1] = r[3];
            }
            #pragma unroll
            for (int mi = 0; mi < 4; mi++)
                #pragma unroll
                for (int nf = 0; nf < 4; nf++)
                    mma16816(acc[mi][nf], a[mi], b[nf]);
        }
        __syncthreads();
    }

    #pragma unroll
    for (int mi = 0; mi < 4; mi++) {
        const int row0 = bRow + wm + mi * 16 + (lane >> 2);
        #pragma unroll
        for (int nf = 0; nf < 4; nf++) {
            const int col = bCol + wn + nf * 8 + (lane & 3) * 2;
            C[(size_t)row0 * N + col]           = acc[mi][nf][0];
            C[(size_t)row0 * N + col + 1]       = acc[mi][nf][1];
            C[(size_t)(row0 + 8) * N + col]     = acc[mi][nf][2];
            C[(size_t)(row0 + 8) * N + col + 1] = acc[mi][nf][3];
        }
    }
}

// -------- fused RMSNorm + RoPE -> fp16 q (pre-scaled), k, v ------------------
__global__ __launch_bounds__(256) void norm_rope_kernel(
    const float* __restrict__ qkv, const int* __restrict__ positions,
    const float* __restrict__ qw, const float* __restrict__ kw,
    __half* __restrict__ qh, __half* __restrict__ kh, __half* __restrict__ vh)
{
    const int t = blockIdx.x;
    const int tid = threadIdx.x;
    const float* row = qkv + (size_t)t * QKV_N;

    __shared__ float red[256];
    __shared__ float s_invq, s_invk;

    float sq = 0.f, sk = 0.f;
    for (int i = tid; i < H_DIM; i += 256) {
        float a = row[i];          sq = fmaf(a, a, sq);
        float b = row[H_DIM + i];  sk = fmaf(b, b, sk);
    }
    red[tid] = sq; __syncthreads();
    for (int s = 128; s > 0; s >>= 1) {
        if (tid < s) red[tid] += red[tid + s];
        __syncthreads();
    }
    if (tid == 0) s_invq = rsqrtf(red[0] / (float)H_DIM + EPS);
    __syncthreads();
    red[tid] = sk; __syncthreads();
    for (int s = 128; s > 0; s >>= 1) {
        if (tid < s) red[tid] += red[tid + s];
        __syncthreads();
    }
    if (tid == 0) s_invk = rsqrtf(red[0] / (float)H_DIM + EPS);
    __syncthreads();

    const float invq = s_invq, invk = s_invk;
    const float pos = (float)positions[t];

    for (int p = tid; p < NH * (HD / 2); p += 256) {
        const int h = p >> 6;
        const int d = p & 63;
        float invf = exp2f(-0.29580576f * (float)d);  // 500000^(-d/64)
        float ang = pos * invf;
        float c, s;
        sincosf(ang, &s, &c);

        const int i1 = h * HD + d;
        const int i2 = i1 + 64;

        float q1 = row[i1] * invq * qw[i1];
        float q2 = row[i2] * invq * qw[i2];
        float k1 = row[H_DIM + i1] * invk * kw[i1];
        float k2 = row[H_DIM + i2] * invk * kw[i2];

        const size_t ob = (size_t)t * H_DIM + h * HD + d;
        qh[ob]      = __float2half((q1 * c - q2 * s) * ATT_SCALE);
        qh[ob + 64] = __float2half((q2 * c + q1 * s) * ATT_SCALE);
        kh[ob]      = __float2half(k1 * c - k2 * s);
        kh[ob + 64] = __float2half(k2 * c + k1 * s);
    }

    for (int i = tid; i < H_DIM; i += 256)
        vh[(size_t)t * H_DIM + i] = __float2half(row[2 * H_DIM + i]);
}

// --------------------- fp16 MMA flash attention ------------------------------
// grid (16 q-tiles of 128, 16 heads), 256 threads = 8 warps x 16 q-rows.
#define BQ 128
#define BK 64
#define KSTR 136   // halves per row (272B, conflict-free for ldmatrix)
#define FLASH_SMEM_BYTES ((BQ * KSTR + 4 * BK * KSTR) * 2)

__global__ __launch_bounds__(256) void flash_mma(
    const __half* __restrict__ qh, const __half* __restrict__ kh,
    const __half* __restrict__ vh, __half* __restrict__ oh)
{
    const int qt = blockIdx.x, h = blockIdx.y;
    const int tid = threadIdx.x, wid = tid >> 5, lane = tid & 31;
    const int wm = wid * 16;

    extern __shared__ __align__(16) __half fsm[];
    __half* Qs = fsm;                    // 128 x 136
    __half* Ks = Qs + BQ * KSTR;         // 2 x (64 x 136)
    __half* Vs = Ks + 2 * BK * KSTR;     // 2 x (64 x 136)

    const int nt = 2 * qt + 2;

    // ---- prologue: Q tile + KV tile 0 via cp.async ----
    {
        const int qr = tid >> 1;
        const int qc = (tid & 1) * 8;
        const size_t qbase = (size_t)(qt * BQ + qr) * H_DIM + h * HD;
        #pragma unroll
        for (int i = 0; i < 8; i++)
            cp_async16(&Qs[qr * KSTR + (qc + i) * 8], &qh[qbase + (qc + i) * 8]);
    }
    {
        const int r  = tid >> 2;
        const int cb = (tid & 3) * 4;
        const size_t base = (size_t)r * H_DIM + h * HD;  // kb = 0
        #pragma unroll
        for (int i = 0; i < 4; i++) {
            cp_async16(&Ks[r * KSTR + (cb + i) * 8], &kh[base + (cb + i) * 8]);
            cp_async16(&Vs[r * KSTR + (cb + i) * 8], &vh[base + (cb + i) * 8]);
        }
    }
    cp_commit();
    cp_wait0();
    __syncthreads();

    // ---- Q fragments (held in registers for the whole kernel) ----
    u32 qf[8][4];
    #pragma unroll
    for (int ks = 0; ks < 8; ks++)
        ldmatrix_x4(qf[ks], &Qs[(wm + (lane & 15)) * KSTR + ks * 16 + (lane >> 4) * 8]);

    float o[16][4];
    #pragma unroll
    for (int nf = 0; nf < 16; nf++)
        #pragma unroll
        for (int r = 0; r < 4; r++) o[nf][r] = 0.f;
    float m0 = -1e30f, m1 = -1e30f, l0 = 0.f, l1 = 0.f;

    for (int kb = 0; kb < nt; kb++) {
        if (kb > 0) { cp_wait0(); __syncthreads(); }

        // prefetch next KV tile into the other buffer
        if (kb + 1 < nt) {
            const int nb = (kb + 1) & 1;
            const int r  = tid >> 2;
            const int cb4 = (tid & 3) * 4;
            const size_t base = (size_t)((kb + 1) * BK + r) * H_DIM + h * HD;
            #pragma unroll
            for (int i = 0; i < 4; i++) {
                cp_async16(&Ks[nb * BK * KSTR + r * KSTR + (cb4 + i) * 8], &kh[base + (cb4 + i) * 8]);
                cp_async16(&Vs[nb * BK * KSTR + r * KSTR + (cb4 + i) * 8], &vh[base + (cb4 + i) * 8]);
            }
            cp_commit();
        }

        const __half* Kb = Ks + (kb & 1) * BK * KSTR;
        const __half* Vb = Vs + (kb & 1) * BK * KSTR;

        // ---- scores: S[16 x 64] = Q Kt ----
        float s[8][4];
        #pragma unroll
        for (int nf = 0; nf < 8; nf++)
            #pragma unroll
            for (int r = 0; r < 4; r++) s[nf][r] = 0.f;

        #pragma unroll
        for (int ks = 0; ks < 8; ks++) {
            u32 bf[8][2];
            #pragma unroll
            for (int ng = 0; ng < 4; ng++) {
                u32 r[4];
                ldmatrix_x4(r, &Kb[(ng * 16 + (lane & 7) + ((lane >> 4) << 3)) * KSTR
                                   + ks * 16 + (((lane >> 3) & 1) << 3)]);
                bf[2 * ng][0] = r[0];     bf[2 * ng][1] = r[1];
                bf[2 * ng + 1][0] = r[2]; bf[2 * ng + 1][1] = r[3];
            }
            #pragma unroll
            for (int nf = 0; nf < 8; nf++)
                mma16816(s[nf], qf[ks], bf[nf]);
        }

        // ---- causal mask (only last two tiles touch the diagonal) ----
        if (kb >= nt - 2) {
            const int grow = qt * BQ + wm + (lane >> 2);
            #pragma unroll
            for (int nf = 0; nf < 8; nf++) {
                const int col = kb * BK + nf * 8 + (lane & 3) * 2;
                if (col     > grow)     s[nf][0] = -1e30f;
                if (col + 1 > grow)     s[nf][1] = -1e30f;
                if (col     > grow + 8) s[nf][2] = -1e30f;
                if (col + 1 > grow + 8) s[nf][3] = -1e30f;
            }
        }

        // ---- online softmax (rows live in 4-lane quads) ----
        float mx0 = -1e30f, mx1 = -1e30f;
        #pragma unroll
        for (int nf = 0; nf < 8; nf++) {
            mx0 = fmaxf(mx0, fmaxf(s[nf][0], s[nf][1]));
            mx1 = fmaxf(mx1, fmaxf(s[nf][2], s[nf][3]));
        }
        mx0 = fmaxf(mx0, __shfl_xor_sync(0xffffffffu, mx0, 1));
        mx0 = fmaxf(mx0, __shfl_xor_sync(0xffffffffu, mx0, 2));
        mx1 = fmaxf(mx1, __shfl_xor_sync(0xffffffffu, mx1, 1));
        mx1 = fmaxf(mx1, __shfl_xor_sync(0xffffffffu, mx1, 2));

        const float mn0 = fmaxf(m0, mx0), mn1 = fmaxf(m1, mx1);
        const float a0 = __expf(m0 - mn0), a1 = __expf(m1 - mn1);
        m0 = mn0; m1 = mn1;

        float ps0 = 0.f, ps1 = 0.f;
        #pragma unroll
        for (int nf = 0; nf < 8; nf++) {
            s[nf][0] = __expf(s[nf][0] - m0); ps0 += s[nf][0];
            s[nf][1] = __expf(s[nf][1] - m0); ps0 += s[nf][1];
            s[nf][2] = __expf(s[nf][2] - m1); ps1 += s[nf][2];
            s[nf][3] = __expf(s[nf][3] - m1); ps1 += s[nf][3];
        }
        ps0 += __shfl_xor_sync(0xffffffffu, ps0, 1);
        ps0 += __shfl_xor_sync(0xffffffffu, ps0, 2);
        ps1 += __shfl_xor_sync(0xffffffffu, ps1, 1);
        ps1 += __shfl_xor_sync(0xffffffffu, ps1, 2);
        l0 = l0 * a0 + ps0;
        l1 = l1 * a1 + ps1;

        #pragma unroll
        for (int nf = 0; nf < 16; nf++) {
            o[nf][0] *= a0; o[nf][1] *= a0;
            o[nf][2] *= a1; o[nf][3] *= a1;
        }

        // ---- O += P @ V ----
        #pragma unroll
        for (int s4 = 0; s4 < 4; s4++) {
            u32 pa[4];
            pa[0] = packh2(s[2 * s4][0],     s[2 * s4][1]);
            pa[1] = packh2(s[2 * s4][2],     s[2 * s4][3]);
            pa[2] = packh2(s[2 * s4 + 1][0], s[2 * s4 + 1][1]);
            pa[3] = packh2(s[2 * s4 + 1][2], s[2 * s4 + 1][3]);
            #pragma unroll
            for (int ng = 0; ng < 8; ng++) {
                u32 r[4];
                ldmatrix_x4_trans(r, &Vb[(s4 * 16 + (lane & 15)) * KSTR
                                         + ng * 16 + (lane >> 4) * 8]);
                mma16816(o[2 * ng],     pa, &r[0]);
                mma16816(o[2 * ng + 1], pa, &r[2]);
            }
        }
    }

    // ---- epilogue: O / l -> fp16 attn [T][H] ----
    const float il0 = 1.f / l0, il1 = 1.f / l1;
    const int row0 = qt * BQ + wm + (lane >> 2);
    #pragma unroll
    for (int nf = 0; nf < 16; nf++) {
        const int col = h * HD + nf * 8 + (lane & 3) * 2;
        __half2 h0 = __floats2half2_rn(o[nf][0] * il0, o[nf][1] * il0);
        __half2 h1 = __floats2half2_rn(o[nf][2] * il1, o[nf][3] * il1);
        *reinterpret_cast<u32*>(&oh[(size_t)row0 * H_DIM + col])       = *reinterpret_cast<u32*>(&h0);
        *reinterpret_cast<u32*>(&oh[(size_t)(row0 + 8) * H_DIM + col]) = *reinterpret_cast<u32*>(&h1);
    }
}

// --------------------------------- launcher ----------------------------------
extern "C" void kernel_launch(void* const* d_in, const int* in_sizes, int n_in,
                              void* d_out, int out_size)
{
    const int*   positions = (const int*)  d_in[0];
    const float* hidden    = (const float*)d_in[1];
    const float* w_qkv     = (const float*)d_in[2];
    const float* q_norm_w  = (const float*)d_in[3];
    const float* k_norm_w  = (const float*)d_in[4];
    const float* w_o       = (const float*)d_in[5];
    float* out = (float*)d_out;

    float *qkv;
    __half *qh, *kh, *vh, *hid_h, *wqkv_h, *wo_h, *attn_h;
    cudaGetSymbolAddress((void**)&qkv,    g_qkv);
    cudaGetSymbolAddress((void**)&qh,     g_qh);
    cudaGetSymbolAddress((void**)&kh,     g_kh);
    cudaGetSymbolAddress((void**)&vh,     g_vh);
    cudaGetSymbolAddress((void**)&hid_h,  g_hid_h);
    cudaGetSymbolAddress((void**)&wqkv_h, g_wqkv_h);
    cudaGetSymbolAddress((void**)&wo_h,   g_wo_h);
    cudaGetSymbolAddress((void**)&attn_h, g_attn_h);

    // 0) fp32 -> fp16 conversions
    {
        int n4 = (T_TOK * H_DIM) / 4;
        f32_to_f16<<<(n4 + 255) / 256, 256>>>(hidden, hid_h, n4);
        int n4w = (H_DIM * QKV_N) / 4;
        f32_to_f16<<<(n4w + 255) / 256, 256>>>(w_qkv, wqkv_h, n4w);
        int n4o = (H_DIM * H_DIM) / 4;
        f32_to_f16<<<(n4o + 255) / 256, 256>>>(w_o, wo_h, n4o);
    }

    // 1) QKV projection (tensor cores)
    {
        dim3 grid(QKV_N / 128, T_TOK / 128);
        hgemm128<<<grid, 256>>>(hid_h, wqkv_h, qkv, T_TOK, QKV_N, H_DIM);
    }

    // 2) RMSNorm + RoPE -> fp16 q/k/v
    norm_rope_kernel<<<T_TOK, 256>>>(qkv, positions, q_norm_w, k_norm_w, qh, kh, vh);

    // 3) causal flash attention (tensor cores)
    {
        cudaFuncSetAttribute(flash_mma,
                             cudaFuncAttributeMaxDynamicSharedMemorySize,
                             FLASH_SMEM_BYTES);
        dim3 grid(T_TOK / BQ, NH);
        flash_mma<<<grid, 256, FLASH_SMEM_BYTES>>>(qh, kh, vh, attn_h);
    }

    // 4) output projection (tensor cores)
    {
        dim3 grid(H_DIM / 128, T_TOK / 128);
        hgemm128<<<grid, 256>>>(attn_h, wo_h, out, T_TOK, H_DIM, H_DIM);
    }
}